// round 13
// baseline (speedup 1.0000x reference)
#include <cuda_runtime.h>
#include <cuda_bf16.h>

#define NMAX 100000
#define MAXDEG 64

// ---------------- scratch (allocation-free) ----------------
__device__ float g_m[(size_t)NMAX * 128];
__device__ float g_h[(size_t)NMAX * 128];
__device__ int g_counts[NMAX];                    // zero-initialized at load
__device__ int g_slots[(size_t)NMAX * MAXDEG];    // incoming src per node
__device__ unsigned short g_wthi[2][128 * 128];
__device__ unsigned short g_wtlo[2][128 * 128];
__device__ float g_b1p[128];                      // pi-permuted bias for layer 1

__device__ __forceinline__ unsigned smem_u32(const void* p) {
    unsigned a;
    asm("{ .reg .u64 t; cvta.to.shared.u64 t, %1; cvt.u32.u64 %0, t; }" : "=r"(a) : "l"(p));
    return a;
}

// W tile layout: row-major 256B rows (n = 0..127, k bf16 cols); 16B chunks
// XOR-swizzled: chunk' = (k>>3) ^ (n & 7).
__device__ __forceinline__ unsigned tile_off(int row, int k) {
    return (unsigned)(row * 256 + ((((k >> 3) ^ (row & 7))) << 4) + (k & 7) * 2);
}

// sigma^{-1} == pi, applied within each 16-group.
__device__ __forceinline__ int perm16(int w) {
    return (w & 2) ? (8 + ((w >> 2) << 1) + (w & 1))
                   : (((w >> 2) << 1) + (w & 1));
}

// ---------------------------------------------------------------------------
// Fused prep: blocks [0,128) convert W^T to bf16 hi/lo tiles
// (layer 0 with sigma^{-1} k-column mapping, layer 1 standard);
// blocks [128, ...) place edges into the slot table. Block 0 also builds b1p.
// ---------------------------------------------------------------------------
__global__ void prep_kernel(const float* __restrict__ W1, const float* __restrict__ W2,
                            const float* __restrict__ b1,
                            const int* __restrict__ src, const int* __restrict__ dst,
                            int* __restrict__ counts, int* __restrict__ slots, int E) {
    if (blockIdx.x < 128) {
        int id = blockIdx.x * 256 + threadIdx.x;   // 0..32767
        int layer = id >> 14;
        int nn = (id >> 7) & 127;
        int k = id & 127;
        const float* W = layer ? W2 : W1;
        float v = W[k * 128 + nn];                 // W^T[n][k]
        __nv_bfloat16 h = __float2bfloat16(v);
        __nv_bfloat16 l = __float2bfloat16(v - __bfloat162float(h));
        int kd = k;
        if (layer == 0) kd = (k & ~15) | perm16(k & 15);   // sigma^{-1} col map
        unsigned idx = tile_off(nn, kd) >> 1;
        g_wthi[layer][idx] = *reinterpret_cast<unsigned short*>(&h);
        g_wtlo[layer][idx] = *reinterpret_cast<unsigned short*>(&l);
        if (blockIdx.x == 0 && threadIdx.x < 128) {
            int q = threadIdx.x;
            g_b1p[q] = b1[(q & ~15) | perm16(q & 15)];     // b1[pi(q)]
        }
    } else {
        int e = (blockIdx.x - 128) * 256 + threadIdx.x;
        if (e < E) {
            int d = dst[e];
            int pos = atomicAdd(&counts[d], 1);
            if (pos < MAXDEG) slots[(size_t)d * MAXDEG + pos] = src[e];
        }
    }
}

// ---------------------------------------------------------------------------
// Warp-autonomous persistent GEMM: C = (relu?)(A) @ W
// Grid 296 x 256 thr (2 CTA/SM). W hi/lo resident in smem (64KB).
// Each WARP owns a 32-row x 64-col slice: 2 m16 tiles x 4 n16 groups, so one
// W-fragment pair (2 ldmatrix.x4) feeds 12 MMAs. A fragments: 4x LDG.128 per
// k16 (sigma ordering, compensated in W prep; no duplication within warp).
// permuteStore=1 -> pi-ordered STG.128 (layer 1); =0 -> standard (layer 2).
// 3 products: Ah*Wh + Ah*Wl + Al*Wh, fp32 accum. No syncs in main loop.
// ---------------------------------------------------------------------------
#define WHI 0
#define WLO 32768
#define GEMM_SMEM 65536

#define MMA_OP(cc, A0, A1, A2, A3, B0, B1)                                       \
    asm volatile("mma.sync.aligned.m16n8k16.row.col.f32.bf16.bf16.f32 "          \
                 "{%0,%1,%2,%3}, {%4,%5,%6,%7}, {%8,%9}, {%0,%1,%2,%3};"         \
                 : "+f"((cc)[0]), "+f"((cc)[1]), "+f"((cc)[2]), "+f"((cc)[3])    \
                 : "r"(A0), "r"(A1), "r"(A2), "r"(A3), "r"(B0), "r"(B1))

__device__ __forceinline__ void split2(float x, float y, unsigned& hi, unsigned& lo) {
    __nv_bfloat162 h = __floats2bfloat162_rn(x, y);
    float2 f = __bfloat1622float2(h);
    __nv_bfloat162 l = __floats2bfloat162_rn(x - f.x, y - f.y);
    hi = *reinterpret_cast<unsigned*>(&h);
    lo = *reinterpret_cast<unsigned*>(&l);
}

__global__ __launch_bounds__(256, 2) void gemm_mma(
    const float* __restrict__ A, const unsigned short* __restrict__ Whi,
    const unsigned short* __restrict__ Wlo, float* __restrict__ C,
    int N, int applyRelu, int numTiles32, int permuteStore) {
    extern __shared__ __align__(128) char smem[];
    const unsigned sb = smem_u32(smem);
    const int tx = threadIdx.x;
    const int lane = tx & 31;

    // Load W hi/lo once (2048 uint4 each).
    {
        const uint4* wh = (const uint4*)Whi;
        const uint4* wl = (const uint4*)Wlo;
        uint4* sh = (uint4*)(smem + WHI);
        uint4* sl = (uint4*)(smem + WLO);
#pragma unroll
        for (int i = 0; i < 8; i++) {
            sh[tx + 256 * i] = wh[tx + 256 * i];
            sl[tx + 256 * i] = wl[tx + 256 * i];
        }
    }
    __syncthreads();   // only sync: W resident for the whole kernel

    const int b_row_l = ((lane >> 4) << 3) + (lane & 7);
    const int b_half = (lane >> 3) & 1;
    const int sw_b = b_row_l & 7;

    const int ar = lane >> 2;        // row within m16 (and +8)
    const int ac = lane & 3;         // float4 col within k16 chunk

    const int warpGlobal = (blockIdx.x * 8) + (tx >> 5);
    const int totalWarps = gridDim.x * 8;
    const int n0 = (warpGlobal & 1) * 64;       // n half owned by this warp
    const float4* A4 = (const float4*)A;

    for (int t32 = warpGlobal >> 1; t32 < numTiles32; t32 += totalWarps >> 1) {
        const int row0 = t32 * 32;
        int r[4];
        r[0] = row0 + ar; r[1] = r[0] + 8; r[2] = r[0] + 16; r[3] = r[0] + 24;

        float c[2][4][8];
#pragma unroll
        for (int t = 0; t < 2; t++)
#pragma unroll
            for (int j = 0; j < 4; j++)
#pragma unroll
                for (int q = 0; q < 8; q++) c[t][j][q] = 0.f;

#pragma unroll
        for (int kk = 0; kk < 8; kk++) {
            float4 v[4];
#pragma unroll
            for (int i = 0; i < 4; i++) {
                v[i] = make_float4(0.f, 0.f, 0.f, 0.f);
                if (r[i] < N) v[i] = __ldg(&A4[(size_t)r[i] * 32 + kk * 4 + ac]);
            }
            if (applyRelu) {
#pragma unroll
                for (int i = 0; i < 4; i++) {
                    v[i].x = fmaxf(v[i].x, 0.f); v[i].y = fmaxf(v[i].y, 0.f);
                    v[i].z = fmaxf(v[i].z, 0.f); v[i].w = fmaxf(v[i].w, 0.f);
                }
            }
            // Frags under sigma: tile t uses v[2t] (rows ar) and v[2t+1] (rows ar+8).
            unsigned ah[2][4], al[2][4];
#pragma unroll
            for (int t = 0; t < 2; t++) {
                split2(v[2 * t].x, v[2 * t].y, ah[t][0], al[t][0]);
                split2(v[2 * t + 1].x, v[2 * t + 1].y, ah[t][1], al[t][1]);
                split2(v[2 * t].z, v[2 * t].w, ah[t][2], al[t][2]);
                split2(v[2 * t + 1].z, v[2 * t + 1].w, ah[t][3], al[t][3]);
            }

            const unsigned kchunk = (unsigned)(((kk * 2 + b_half) ^ sw_b) << 4);
#pragma unroll
            for (int j = 0; j < 4; j++) {        // n16 groups in this n half
                const unsigned roff = (unsigned)((n0 + j * 16 + b_row_l) * 256) + kchunk;
                unsigned wh0, wh1, wh2, wh3, wl0, wl1, wl2, wl3;
                asm volatile("ldmatrix.sync.aligned.m8n8.x4.shared.b16 {%0,%1,%2,%3}, [%4];"
                             : "=r"(wh0), "=r"(wh1), "=r"(wh2), "=r"(wh3)
                             : "r"(sb + WHI + roff));
                asm volatile("ldmatrix.sync.aligned.m8n8.x4.shared.b16 {%0,%1,%2,%3}, [%4];"
                             : "=r"(wl0), "=r"(wl1), "=r"(wl2), "=r"(wl3)
                             : "r"(sb + WLO + roff));
#pragma unroll
                for (int t = 0; t < 2; t++) {
                    MMA_OP(c[t][j] + 0, ah[t][0], ah[t][1], ah[t][2], ah[t][3], wh0, wh1);
                    MMA_OP(c[t][j] + 4, ah[t][0], ah[t][1], ah[t][2], ah[t][3], wh2, wh3);
                    MMA_OP(c[t][j] + 0, al[t][0], al[t][1], al[t][2], al[t][3], wh0, wh1);
                    MMA_OP(c[t][j] + 4, al[t][0], al[t][1], al[t][2], al[t][3], wh2, wh3);
                    MMA_OP(c[t][j] + 0, ah[t][0], ah[t][1], ah[t][2], ah[t][3], wl0, wl1);
                    MMA_OP(c[t][j] + 4, ah[t][0], ah[t][1], ah[t][2], ah[t][3], wl2, wl3);
                }
            }
        }

        if (permuteStore) {
#pragma unroll
            for (int t = 0; t < 2; t++) {
                const int ra = r[2 * t];
                const int rb = r[2 * t + 1];
                if (ra < N) {
                    float4* Crow = (float4*)(C + (size_t)ra * 128 + n0) + (lane & 3);
#pragma unroll
                    for (int j = 0; j < 4; j++)
                        Crow[j * 4] = make_float4(c[t][j][0], c[t][j][1], c[t][j][4], c[t][j][5]);
                }
                if (rb < N) {
                    float4* Crow = (float4*)(C + (size_t)rb * 128 + n0) + (lane & 3);
#pragma unroll
                    for (int j = 0; j < 4; j++)
                        Crow[j * 4] = make_float4(c[t][j][2], c[t][j][3], c[t][j][6], c[t][j][7]);
                }
            }
        } else {
#pragma unroll
            for (int t = 0; t < 2; t++) {
                const int ra = r[2 * t];
                const int rb = r[2 * t + 1];
                if (ra < N) {
                    float* Crow = C + (size_t)ra * 128 + n0 + (lane & 3) * 2;
#pragma unroll
                    for (int j = 0; j < 4; j++) {
                        *(float2*)(Crow + j * 16) = make_float2(c[t][j][0], c[t][j][1]);
                        *(float2*)(Crow + j * 16 + 8) = make_float2(c[t][j][4], c[t][j][5]);
                    }
                }
                if (rb < N) {
                    float* Crow = C + (size_t)rb * 128 + n0 + (lane & 3) * 2;
#pragma unroll
                    for (int j = 0; j < 4; j++) {
                        *(float2*)(Crow + j * 16) = make_float2(c[t][j][2], c[t][j][3]);
                        *(float2*)(Crow + j * 16 + 8) = make_float2(c[t][j][6], c[t][j][7]);
                    }
                }
            }
        }
    }
}

// ---------------------------------------------------------------------------
// Pull aggregation (R8 version, proven local optimum): one warp per node.
// Permutation-transparent: sums rows elementwise.
// ---------------------------------------------------------------------------
__global__ void aggregate_kernel(const float* __restrict__ m,
                                 const int* __restrict__ counts,
                                 const int* __restrict__ slots,
                                 const float* __restrict__ bias,
                                 float* __restrict__ out, int N, int zeroCounts) {
    int warp = (blockIdx.x * blockDim.x + threadIdx.x) >> 5;
    int lane = threadIdx.x & 31;
    if (warp >= N) return;
    int cnt = counts[warp];
    if (cnt > MAXDEG) cnt = MAXDEG;
    const int* sl = slots + (size_t)warp * MAXDEG;
    float4 acc = ((const float4*)bias)[lane];
    int idx = 0;
    for (; idx + 4 <= cnt; idx += 4) {
        int s0 = __ldg(&sl[idx]);
        int s1 = __ldg(&sl[idx + 1]);
        int s2 = __ldg(&sl[idx + 2]);
        int s3 = __ldg(&sl[idx + 3]);
        float4 v0 = ((const float4*)(m + (size_t)s0 * 128))[lane];
        float4 v1 = ((const float4*)(m + (size_t)s1 * 128))[lane];
        float4 v2 = ((const float4*)(m + (size_t)s2 * 128))[lane];
        float4 v3 = ((const float4*)(m + (size_t)s3 * 128))[lane];
        acc.x += v0.x + v1.x + v2.x + v3.x;
        acc.y += v0.y + v1.y + v2.y + v3.y;
        acc.z += v0.z + v1.z + v2.z + v3.z;
        acc.w += v0.w + v1.w + v2.w + v3.w;
    }
    for (; idx < cnt; idx++) {
        int s = __ldg(&sl[idx]);
        float4 v = ((const float4*)(m + (size_t)s * 128))[lane];
        acc.x += v.x; acc.y += v.y; acc.z += v.z; acc.w += v.w;
    }
    ((float4*)(out + (size_t)warp * 128))[lane] = acc;
    if (zeroCounts && lane == 0) ((int*)counts)[warp] = 0;
}

// ---------------------------------------------------------------------------
extern "C" void kernel_launch(void* const* d_in, const int* in_sizes, int n_in,
                              void* d_out, int out_size) {
    const float* x  = (const float*)d_in[0];
    const int*   ei = (const int*)d_in[1];
    const float* W1 = (const float*)d_in[2];
    const float* b1 = (const float*)d_in[3];
    const float* W2 = (const float*)d_in[4];
    const float* b2 = (const float*)d_in[5];
    float* out = (float*)d_out;

    const int N = in_sizes[0] / 128;
    const int E = in_sizes[1] / 2;
    const int* src = ei;
    const int* dst = ei + E;

    float* gm; float* gh;
    int *counts, *slots;
    unsigned short *wthi, *wtlo;
    float* b1p;
    cudaGetSymbolAddress((void**)&gm, g_m);
    cudaGetSymbolAddress((void**)&gh, g_h);
    cudaGetSymbolAddress((void**)&counts, g_counts);
    cudaGetSymbolAddress((void**)&slots, g_slots);
    cudaGetSymbolAddress((void**)&wthi, g_wthi);
    cudaGetSymbolAddress((void**)&wtlo, g_wtlo);
    cudaGetSymbolAddress((void**)&b1p, g_b1p);

    cudaFuncSetAttribute(gemm_mma, cudaFuncAttributeMaxDynamicSharedMemorySize, GEMM_SMEM);

    const int numTiles32 = (N + 31) / 32;
    const int gemmGrid = 296;                       // 2 CTA/SM persistent
    const int prepGrid = 128 + (E + 255) / 256;
    const int aggGrid = (N + 7) / 8;

    // Fused prep: W conversion (+sigma^{-1} for W1), b1 perm, slot-table build.
    prep_kernel<<<prepGrid, 256>>>(W1, W2, b1, src, dst, counts, slots, E);

    // Layer 1: m (pi-permuted columns) = x @ W1; h_perm = agg(m) + b1p.
    gemm_mma<<<gemmGrid, 256, GEMM_SMEM>>>(x, wthi, wtlo, gm, N, 0, numTiles32, 1);
    aggregate_kernel<<<aggGrid, 256>>>(gm, counts, slots, b1p, gh, N, 0);

    // Layer 2: sigma-fragment load of h_perm cancels pi -> standard W2, standard store.
    gemm_mma<<<gemmGrid, 256, GEMM_SMEM>>>(gh, wthi + 128 * 128, wtlo + 128 * 128, gm, N, 1, numTiles32, 0);
    aggregate_kernel<<<aggGrid, 256>>>(gm, counts, slots, b2, out, N, 1);
}